// round 1
// baseline (speedup 1.0000x reference)
#include <cuda_runtime.h>
#include <math.h>

#define NTHREADS 256
#define NCLS 1000
#define KPT 4          // ceil(1000/256)
#define NT 800

// Block-wide sum with a FIXED reduction tree (butterfly shfl -> shared -> butterfly).
// The leading __syncthreads protects sh/shb reuse from the previous call.
__device__ __forceinline__ float blk_sum(float v, float* sh, float* shb) {
#pragma unroll
    for (int o = 16; o > 0; o >>= 1) v += __shfl_xor_sync(0xffffffffu, v, o);
    __syncthreads();
    if ((threadIdx.x & 31) == 0) sh[threadIdx.x >> 5] = v;
    __syncthreads();
    if (threadIdx.x < 32) {
        float w = (threadIdx.x < (NTHREADS / 32)) ? sh[threadIdx.x] : 0.0f;
#pragma unroll
        for (int o = 4; o > 0; o >>= 1) w += __shfl_xor_sync(0xffffffffu, w, o);
        if (threadIdx.x == 0) *shb = w;
    }
    __syncthreads();
    return *shb;
}

__device__ __forceinline__ float blk_max(float v, float* sh, float* shb) {
#pragma unroll
    for (int o = 16; o > 0; o >>= 1) v = fmaxf(v, __shfl_xor_sync(0xffffffffu, v, o));
    __syncthreads();
    if ((threadIdx.x & 31) == 0) sh[threadIdx.x >> 5] = v;
    __syncthreads();
    if (threadIdx.x < 32) {
        float w = (threadIdx.x < (NTHREADS / 32)) ? sh[threadIdx.x] : -INFINITY;
#pragma unroll
        for (int o = 4; o > 0; o >>= 1) w = fmaxf(w, __shfl_xor_sync(0xffffffffu, w, o));
        if (threadIdx.x == 0) *shb = w;
    }
    __syncthreads();
    return *shb;
}

// S(t) = sum_j expf( fl(l_j / t) - fl(m / t) ), replicating the reference's
// per-element rounding (division then subtract then exp).
__device__ __forceinline__ float eval_S(const float r[KPT], float t, float xm,
                                        float* sh, float* shb) {
    float s = 0.0f;
#pragma unroll
    for (int k = 0; k < KPT; k++) {
        int idx = threadIdx.x + k * NTHREADS;
        if (idx < NCLS) {
            s += expf(__fsub_rn(__fdiv_rn(r[k], t), xm));
        }
    }
    return blk_sum(s, sh, shb);
}

// conf_t(t) = expf(mx - (logf(S) + mx)) -- exact rounding sequence of
// jax logsumexp (max + log(sum(exp(x-max)))) followed by exp(max - lse).
__device__ __forceinline__ float eval_conf_t(const float r[KPT], float t, float m,
                                             float* sh, float* shb) {
    float xm = __fdiv_rn(m, t);
    float S = eval_S(r, t, xm, sh, shb);
    float lse = __fadd_rn(logf(S), xm);
    return expf(__fsub_rn(xm, lse));
}

__global__ __launch_bounds__(NTHREADS)
void logit_compression_kernel(const float* __restrict__ logits,
                              float* __restrict__ out) {
    __shared__ float sh[NTHREADS / 32];
    __shared__ float shb;

    const int row = blockIdx.x;
    const int tid = threadIdx.x;
    const float* lrow = logits + row * NCLS;
    float* orow = out + row * NCLS;

    // Cache the row in registers.
    float r[KPT];
#pragma unroll
    for (int k = 0; k < KPT; k++) {
        int idx = tid + k * NTHREADS;
        r[k] = (idx < NCLS) ? lrow[idx] : -INFINITY;
    }

    // Row max (exact; any order).
    float mv = -INFINITY;
#pragma unroll
    for (int k = 0; k < KPT; k++) mv = fmaxf(mv, r[k]);
    const float m = blk_max(mv, sh, &shb);

    // Original confidence: conf = fl(1 / S1) with S1 = sum exp(l - m).
    // t = 1.0f makes __fdiv_rn(l, 1.0f) == l exactly, so eval_S(1.0) == S1.
    const float S1 = eval_S(r, 1.0f, m, sh, &shb);
    const float conf = __fdiv_rn(1.0f, S1);

    // Bin assignment (first bin with upper > conf && lower <= conf; default 0).
    int b = 0;
    if ((1.0f / 3.0f) > conf && 0.0f <= conf)                 b = 0;
    else if ((2.0f / 3.0f) > conf && (1.0f / 3.0f) <= conf)   b = 1;
    else if (1.0f > conf && (2.0f / 3.0f) <= conf)            b = 2;

    const float BLs[3]  = {0.0f, 1.0f / 3.0f, 2.0f / 3.0f};
    const float NBLs[3] = {0.8f, 0.86666666666f, 0.93333333333f};
    // new_conf = NBL[b] + (1/15) * ((conf - BL[b]) / 0.2666666667), fp32,
    // _rn intrinsics prevent FMA contraction.
    const float nc = __fadd_rn(
        NBLs[b],
        __fmul_rn((float)(1.0 / 15.0),
                  __fdiv_rn(__fsub_rn(conf, BLs[b]), 0.2666666667f)));

    // conf_t(j) is monotone non-decreasing in j (temps decrease, terms shrink,
    // fixed fp32 reduction tree is order-preserving). Binary search for the
    // smallest j with conf_t(j) - nc >= -TOL; band-check that index.
    int lo = 0, hi = NT;
    while (lo < hi) {
        int mid = (lo + hi) >> 1;
        float t = __fsub_rn(1.0f, __fmul_rn(0.00125f, (float)mid));
        float ct = eval_conf_t(r, t, m, sh, &shb);
        // ct is block-broadcast => branch is uniform.
        if (__fsub_rn(ct, nc) >= -0.01f) hi = mid;
        else lo = mid + 1;
    }

    bool found = false;
    float tj = 1.0f;
    if (lo < NT) {
        float t = __fsub_rn(1.0f, __fmul_rn(0.00125f, (float)lo));
        float ct = eval_conf_t(r, t, m, sh, &shb);
        float g = __fsub_rn(ct, nc);
        found = (fabsf(g) <= 0.01f);
        tj = t;
    }

    // out = found ? logits / chosen_temp : logits
#pragma unroll
    for (int k = 0; k < KPT; k++) {
        int idx = tid + k * NTHREADS;
        if (idx < NCLS) {
            orow[idx] = found ? __fdiv_rn(r[k], tj) : r[k];
        }
    }
}

extern "C" void kernel_launch(void* const* d_in, const int* in_sizes, int n_in,
                              void* d_out, int out_size) {
    const float* logits = (const float*)d_in[0];
    float* out = (float*)d_out;
    int B = in_sizes[0] / NCLS;   // 128 rows
    logit_compression_kernel<<<B, NTHREADS>>>(logits, out);
}

// round 2
// speedup vs baseline: 1.4065x; 1.4065x over previous
#include <cuda_runtime.h>
#include <math.h>

#define NTHREADS 256
#define NW 8            // warps per block = parallel probes per round
#define NCLS 1000
#define NPAD 1024
#define KPT 4           // elements per thread (block-wide layout)
#define NT 800
#define TSTEP 0.00125f
#define TOL 0.01f

__global__ __launch_bounds__(NTHREADS)
void logit_compression_kernel(const float* __restrict__ logits,
                              float* __restrict__ out) {
    __shared__ float dsm[NPAD];    // d_j = fl(l_j - m), padded with -inf
    __shared__ float red[NW];
    __shared__ float ctsh[NW];
    __shared__ float bsh;

    const int tid  = threadIdx.x;
    const int lane = tid & 31;
    const int w    = tid >> 5;
    const int row  = blockIdx.x;
    const float* lrow = logits + row * NCLS;
    float* orow = out + row * NCLS;

    // ---- load row (kept in registers for the output pass) ----
    float r[KPT];
#pragma unroll
    for (int k = 0; k < KPT; k++) {
        int idx = tid + k * NTHREADS;
        r[k] = (idx < NCLS) ? lrow[idx] : -INFINITY;
    }

    // ---- block max (exact) ----
    float mv = fmaxf(fmaxf(r[0], r[1]), fmaxf(r[2], r[3]));
#pragma unroll
    for (int o = 16; o > 0; o >>= 1) mv = fmaxf(mv, __shfl_xor_sync(0xffffffffu, mv, o));
    if (lane == 0) red[w] = mv;
    __syncthreads();
    if (tid < 32) {
        float v = (tid < NW) ? red[tid] : -INFINITY;
#pragma unroll
        for (int o = 4; o > 0; o >>= 1) v = fmaxf(v, __shfl_xor_sync(0xffffffffu, v, o));
        if (tid == 0) bsh = v;
    }
    __syncthreads();
    const float m = bsh;
    __syncthreads();   // bsh read by all before reuse below

    // ---- d = fl(l - m) into smem; S1 with ACCURATE expf (reference-exact terms) ----
    float s1 = 0.0f;
#pragma unroll
    for (int k = 0; k < KPT; k++) {
        float dk = __fsub_rn(r[k], m);     // -inf for padding lanes
        dsm[tid + k * NTHREADS] = dk;
        s1 += expf(dk);                    // expf(-inf) == 0
    }
#pragma unroll
    for (int o = 16; o > 0; o >>= 1) s1 += __shfl_xor_sync(0xffffffffu, s1, o);
    if (lane == 0) red[w] = s1;
    __syncthreads();
    if (tid < 32) {
        float v = (tid < NW) ? red[tid] : 0.0f;
#pragma unroll
        for (int o = 4; o > 0; o >>= 1) v += __shfl_xor_sync(0xffffffffu, v, o);
        if (tid == 0) bsh = v;
    }
    __syncthreads();   // also publishes dsm to all warps
    const float S1 = bsh;

    // ---- original confidence, bin, target confidence ----
    const float conf = __fdiv_rn(1.0f, S1);
    int b = (conf >= (2.0f / 3.0f)) ? 2 : (conf >= (1.0f / 3.0f)) ? 1 : 0;
    const float BL  = (b == 0) ? 0.0f : (b == 1) ? (1.0f / 3.0f) : (2.0f / 3.0f);
    const float NBL = (b == 0) ? 0.8f : (b == 1) ? 0.86666666666f : 0.93333333333f;
    const float nc  = __fadd_rn(NBL,
                     __fmul_rn((float)(1.0 / 15.0),
                               __fdiv_rn(__fsub_rn(conf, BL), 0.2666666667f)));

    // ---- 8-way parallel search for first j with conf_t(j) >= nc - TOL ----
    // conf_t(j) is monotone non-decreasing in j (temps decrease, terms shrink,
    // fixed summation tree is order-preserving).
    int lo = 0, hi = NT;        // answer in [lo, hi]; hi==NT means "none found yet"
    float ct_hi = 0.0f;         // ct at index hi (valid whenever hi < NT)
    const float4* d4 = (const float4*)dsm;

    while (lo < hi) {
        const int range  = hi - lo;
        const int stride = (range + NW - 1) >> 3;     // ceil(range/8), >= 1
        const int probe  = lo + w * stride;
        float ctv = 0.0f;
        if (probe < hi) {                             // warp-uniform branch
            float t    = __fsub_rn(1.0f, __fmul_rn(TSTEP, (float)probe));
            float invt = __fdiv_rn(1.0f, t);
            float s = 0.0f;
#pragma unroll
            for (int k = 0; k < 8; k++) {
                float4 v = d4[lane + k * 32];
                s += __expf(__fmul_rn(v.x, invt));
                s += __expf(__fmul_rn(v.y, invt));
                s += __expf(__fmul_rn(v.z, invt));
                s += __expf(__fmul_rn(v.w, invt));
            }
#pragma unroll
            for (int o = 16; o > 0; o >>= 1) s += __shfl_xor_sync(0xffffffffu, s, o);
            float mx  = __fmul_rn(m, invt);
            float lse = __fadd_rn(logf(s), mx);
            ctv = expf(__fsub_rn(mx, lse));
        }
        if (lane == 0) ctsh[w] = ctv;
        __syncthreads();

        // Every thread redundantly computes the new interval (deterministic).
        int first = -1, lastvalid = -1;
#pragma unroll
        for (int i = 0; i < NW; i++) {
            int p = lo + i * stride;
            if (p < hi) {
                lastvalid = i;
                if (first < 0 && __fsub_rn(ctsh[i], nc) >= -TOL) first = i;
            }
        }
        if (first >= 0) {
            ct_hi = ctsh[first];
            hi = lo + first * stride;
            if (first > 0) lo = lo + (first - 1) * stride + 1;
            // first == 0 -> hi == lo -> done
        } else {
            lo = lo + lastvalid * stride + 1;
        }
        __syncthreads();   // protect ctsh reuse next round
    }

    // ---- band check + output ----
    bool found = false;
    float tj = 1.0f;
    if (hi < NT) {
        float g = __fsub_rn(ct_hi, nc);      // >= -TOL by construction
        found = (fabsf(g) <= TOL);
        tj = __fsub_rn(1.0f, __fmul_rn(TSTEP, (float)hi));
    }
#pragma unroll
    for (int k = 0; k < KPT; k++) {
        int idx = tid + k * NTHREADS;
        if (idx < NCLS) orow[idx] = found ? __fdiv_rn(r[k], tj) : r[k];
    }
}

extern "C" void kernel_launch(void* const* d_in, const int* in_sizes, int n_in,
                              void* d_out, int out_size) {
    const float* logits = (const float*)d_in[0];
    float* out = (float*)d_out;
    int B = in_sizes[0] / NCLS;   // 128 rows
    logit_compression_kernel<<<B, NTHREADS>>>(logits, out);
}